// round 2
// baseline (speedup 1.0000x reference)
#include <cuda_runtime.h>
#include <math.h>

#define Tn 512
#define Vn 512
#define Fn 12
#define En 512
#define Hn 8
#define Dn 64
#define VFn (Vn*Fn)
#define Mbig (Vn*Tn)

// ---------------- scratch (static device allocations; no cudaMalloc) ----------
static __device__ float g_tln[Tn*En];                 // 1 MB
static __device__ float g_vln[VFn*En];                // 12.6 MB
static __device__ float g_q[Tn*En];                   // 1 MB
static __device__ float g_k[VFn*En];                  // 12.6 MB
static __device__ float g_v[VFn*En];                  // 12.6 MB
static __device__ float g_attn[(size_t)Mbig*En];      // 512 MB
static __device__ float g_o[(size_t)Mbig*En];         // 512 MB

// ---------------- row LayerNorm over width 512 -------------------------------
// one block (128 threads) per row; each thread owns one float4
__global__ __launch_bounds__(128) void ln_kernel(
    const float* __restrict__ x, const float* __restrict__ g,
    const float* __restrict__ b, float* __restrict__ out)
{
    int row = blockIdx.x;
    int tid = threadIdx.x;
    const float4* x4 = (const float4*)(x + (size_t)row * En);
    float4 v = x4[tid];
    float s  = v.x + v.y + v.z + v.w;
    float ss = v.x*v.x + v.y*v.y + v.z*v.z + v.w*v.w;
    #pragma unroll
    for (int o = 16; o > 0; o >>= 1) {
        s  += __shfl_xor_sync(0xffffffffu, s,  o);
        ss += __shfl_xor_sync(0xffffffffu, ss, o);
    }
    __shared__ float sm[4], sm2[4];
    int w = tid >> 5, l = tid & 31;
    if (l == 0) { sm[w] = s; sm2[w] = ss; }
    __syncthreads();
    s  = sm[0] + sm[1] + sm[2] + sm[3];
    ss = sm2[0] + sm2[1] + sm2[2] + sm2[3];
    float mean = s * (1.0f / En);
    float var  = ss * (1.0f / En) - mean * mean;
    float rstd = rsqrtf(var + 1e-5f);
    float4 gg = ((const float4*)g)[tid];
    float4 bb = ((const float4*)b)[tid];
    float4 o;
    o.x = (v.x - mean) * rstd * gg.x + bb.x;
    o.y = (v.y - mean) * rstd * gg.y + bb.y;
    o.z = (v.z - mean) * rstd * gg.z + bb.z;
    o.w = (v.w - mean) * rstd * gg.w + bb.w;
    ((float4*)(out + (size_t)row * En))[tid] = o;
}

// ---------------- SIMT SGEMM: C[M,512] = A[M,512] @ W[512,512]^T + bias (+addsrc)
// BM=BN=128, BK=16, 256 threads, 8x8 per-thread tile, double-buffered smem
template<bool ADD>
__global__ __launch_bounds__(256) void gemm_kernel(
    const float* __restrict__ A, const float* __restrict__ W,
    const float* __restrict__ bias, const float* __restrict__ addsrc,
    float* __restrict__ C)
{
    constexpr int BM = 128, BN = 128, BK = 16, LDS_P = BM + 4;
    __shared__ float As[2][BK][LDS_P];
    __shared__ float Bs[2][BK][LDS_P];

    int tid = threadIdx.x;
    int bm = blockIdx.x, bn = blockIdx.y;
    int tx = tid & 15, ty = tid >> 4;

    const float* Ab = A + (size_t)bm * BM * 512;
    const float* Wb = W + (size_t)bn * BN * 512;

    float acc[8][8];
    #pragma unroll
    for (int i = 0; i < 8; i++)
        #pragma unroll
        for (int j = 0; j < 8; j++) acc[i][j] = 0.0f;

    float pa[8], pb[8];

    // prologue: tile 0 -> smem[0]
    {
        int k0 = 0;
        #pragma unroll
        for (int it = 0; it < 2; it++) {
            int r = tid + 256 * it;
            int row = r >> 2, kc = (r & 3) << 2;
            float4 va = *(const float4*)(Ab + (size_t)row * 512 + k0 + kc);
            float4 vb = *(const float4*)(Wb + (size_t)row * 512 + k0 + kc);
            As[0][kc + 0][row] = va.x; As[0][kc + 1][row] = va.y;
            As[0][kc + 2][row] = va.z; As[0][kc + 3][row] = va.w;
            Bs[0][kc + 0][row] = vb.x; Bs[0][kc + 1][row] = vb.y;
            Bs[0][kc + 2][row] = vb.z; Bs[0][kc + 3][row] = vb.w;
        }
    }
    __syncthreads();

    const int NT = 512 / BK; // 32
    for (int kt = 0; kt < NT; kt++) {
        int cur = kt & 1;
        if (kt + 1 < NT) {
            int k0 = (kt + 1) * BK;
            #pragma unroll
            for (int it = 0; it < 2; it++) {
                int r = tid + 256 * it;
                int row = r >> 2, kc = (r & 3) << 2;
                float4 va = *(const float4*)(Ab + (size_t)row * 512 + k0 + kc);
                float4 vb = *(const float4*)(Wb + (size_t)row * 512 + k0 + kc);
                pa[it*4+0] = va.x; pa[it*4+1] = va.y; pa[it*4+2] = va.z; pa[it*4+3] = va.w;
                pb[it*4+0] = vb.x; pb[it*4+1] = vb.y; pb[it*4+2] = vb.z; pb[it*4+3] = vb.w;
            }
        }
        #pragma unroll
        for (int k = 0; k < BK; k++) {
            float a[8], b[8];
            *(float4*)(a)     = *(const float4*)&As[cur][k][ty * 8];
            *(float4*)(a + 4) = *(const float4*)&As[cur][k][ty * 8 + 4];
            *(float4*)(b)     = *(const float4*)&Bs[cur][k][tx * 8];
            *(float4*)(b + 4) = *(const float4*)&Bs[cur][k][tx * 8 + 4];
            #pragma unroll
            for (int i = 0; i < 8; i++)
                #pragma unroll
                for (int j = 0; j < 8; j++)
                    acc[i][j] = fmaf(a[i], b[j], acc[i][j]);
        }
        if (kt + 1 < NT) {
            int nb = (kt + 1) & 1;
            #pragma unroll
            for (int it = 0; it < 2; it++) {
                int r = tid + 256 * it;
                int row = r >> 2, kc = (r & 3) << 2;
                As[nb][kc + 0][row] = pa[it*4+0]; As[nb][kc + 1][row] = pa[it*4+1];
                As[nb][kc + 2][row] = pa[it*4+2]; As[nb][kc + 3][row] = pa[it*4+3];
                Bs[nb][kc + 0][row] = pb[it*4+0]; Bs[nb][kc + 1][row] = pb[it*4+1];
                Bs[nb][kc + 2][row] = pb[it*4+2]; Bs[nb][kc + 3][row] = pb[it*4+3];
            }
            __syncthreads();
        }
    }

    int row0 = bm * BM + ty * 8;
    int col0 = bn * BN + tx * 8;
    float4 bi0 = *(const float4*)(bias + col0);
    float4 bi1 = *(const float4*)(bias + col0 + 4);
    #pragma unroll
    for (int i = 0; i < 8; i++) {
        size_t base = (size_t)(row0 + i) * 512 + col0;
        float4 v0, v1;
        v0.x = acc[i][0] + bi0.x; v0.y = acc[i][1] + bi0.y;
        v0.z = acc[i][2] + bi0.z; v0.w = acc[i][3] + bi0.w;
        v1.x = acc[i][4] + bi1.x; v1.y = acc[i][5] + bi1.y;
        v1.z = acc[i][6] + bi1.z; v1.w = acc[i][7] + bi1.w;
        if (ADD) {
            float4 a0 = *(const float4*)(addsrc + base);
            float4 a1 = *(const float4*)(addsrc + base + 4);
            v0.x += a0.x; v0.y += a0.y; v0.z += a0.z; v0.w += a0.w;
            v1.x += a1.x; v1.y += a1.y; v1.z += a1.z; v1.w += a1.w;
        }
        *(float4*)(C + base)     = v0;
        *(float4*)(C + base + 4) = v1;
    }
}

// ---------------- fused attention: logits + softmax(frames) + weighted sum ----
// grid: (V, T/128).  block: 256 threads.
// smem: k_s[12][512], v_s[12][512], w_s[8][12][128]  = 96 KB dynamic
__global__ __launch_bounds__(256) void attn_kernel(
    const float* __restrict__ q, const float* __restrict__ kk,
    const float* __restrict__ vv, float* __restrict__ attn)
{
    extern __shared__ float smem[];
    float* k_s = smem;                    // 12*512
    float* v_s = smem + Fn * En;          // 12*512
    float* w_s = smem + 2 * Fn * En;      // 8*12*128

    int vb  = blockIdx.x;
    int tt  = blockIdx.y;                 // t-tile of 128
    int tid = threadIdx.x;

    // stage k,v for this video
    {
        const float4* kg = (const float4*)(kk + (size_t)vb * Fn * En);
        const float4* vg = (const float4*)(vv + (size_t)vb * Fn * En);
        float4* k4 = (float4*)k_s;
        float4* v4 = (float4*)v_s;
        for (int i = tid; i < Fn * En / 4; i += 256) { k4[i] = kg[i]; v4[i] = vg[i]; }
    }
    __syncthreads();

    // ---- logits + softmax: warp h owns head h; lane owns 4 t-rows -----------
    int h = tid >> 5, lane = tid & 31;
    int tbase = tt * 128 + lane * 4;

    float acc[Fn][4];
    #pragma unroll
    for (int f = 0; f < Fn; f++)
        #pragma unroll
        for (int i = 0; i < 4; i++) acc[f][i] = 0.0f;

    const float* q0 = q + (size_t)(tbase + 0) * En + h * Dn;
    const float* q1 = q + (size_t)(tbase + 1) * En + h * Dn;
    const float* q2 = q + (size_t)(tbase + 2) * En + h * Dn;
    const float* q3 = q + (size_t)(tbase + 3) * En + h * Dn;
    const float* kb = k_s + h * Dn;

    for (int dc = 0; dc < Dn; dc += 8) {
        float qf[4][8];
        *(float4*)&qf[0][0] = *(const float4*)(q0 + dc);
        *(float4*)&qf[0][4] = *(const float4*)(q0 + dc + 4);
        *(float4*)&qf[1][0] = *(const float4*)(q1 + dc);
        *(float4*)&qf[1][4] = *(const float4*)(q1 + dc + 4);
        *(float4*)&qf[2][0] = *(const float4*)(q2 + dc);
        *(float4*)&qf[2][4] = *(const float4*)(q2 + dc + 4);
        *(float4*)&qf[3][0] = *(const float4*)(q3 + dc);
        *(float4*)&qf[3][4] = *(const float4*)(q3 + dc + 4);
        #pragma unroll
        for (int d = 0; d < 8; d++) {
            #pragma unroll
            for (int f = 0; f < Fn; f++) {
                float kv = kb[f * En + dc + d];   // broadcast within warp
                #pragma unroll
                for (int i = 0; i < 4; i++)
                    acc[f][i] = fmaf(kv, qf[i][d], acc[f][i]);
            }
        }
    }

    const float scale = 0.125f; // 1/sqrt(64)
    #pragma unroll
    for (int i = 0; i < 4; i++) {
        float m = -1e30f;
        #pragma unroll
        for (int f = 0; f < Fn; f++) m = fmaxf(m, acc[f][i] * scale);
        float e[Fn];
        float s = 0.0f;
        #pragma unroll
        for (int f = 0; f < Fn; f++) { e[f] = __expf(acc[f][i] * scale - m); s += e[f]; }
        float inv = 1.0f / s;
        #pragma unroll
        for (int f = 0; f < Fn; f++)
            w_s[(h * Fn + f) * 128 + lane * 4 + i] = e[f] * inv;
    }
    __syncthreads();

    // ---- attn = sum_f w * v ; thread owns an e-quad, loops 64 t-rows --------
    int ec   = tid & 127;
    int half = tid >> 7;
    int e0   = ec * 4;
    int hh   = e0 >> 6;
    #pragma unroll 4
    for (int tl = 0; tl < 64; tl++) {
        int t_local = half * 64 + tl;
        float4 o = make_float4(0.f, 0.f, 0.f, 0.f);
        #pragma unroll
        for (int f = 0; f < Fn; f++) {
            float w   = w_s[(hh * Fn + f) * 128 + t_local];
            float4 vq = *(const float4*)&v_s[f * En + e0];
            o.x = fmaf(w, vq.x, o.x);
            o.y = fmaf(w, vq.y, o.y);
            o.z = fmaf(w, vq.z, o.z);
            o.w = fmaf(w, vq.w, o.w);
        }
        size_t t = (size_t)tt * 128 + t_local;
        *(float4*)(attn + ((size_t)vb * Tn + t) * En + e0) = o;
    }
}

// ---------------- launch ------------------------------------------------------
extern "C" void kernel_launch(void* const* d_in, const int* in_sizes, int n_in,
                              void* d_out, int out_size)
{
    const float* text  = (const float*)d_in[0];
    const float* video = (const float*)d_in[1];
    const float* Wq = (const float*)d_in[2];  const float* bq = (const float*)d_in[3];
    const float* Wk = (const float*)d_in[4];  const float* bk = (const float*)d_in[5];
    const float* Wv = (const float*)d_in[6];  const float* bv = (const float*)d_in[7];
    const float* Wo = (const float*)d_in[8];  const float* bo = (const float*)d_in[9];
    const float* Wl = (const float*)d_in[10]; const float* bl = (const float*)d_in[11];
    const float* ln1g = (const float*)d_in[12]; const float* ln1b = (const float*)d_in[13];
    const float* ln2g = (const float*)d_in[14]; const float* ln2b = (const float*)d_in[15];
    const float* ln3g = (const float*)d_in[16]; const float* ln3b = (const float*)d_in[17];
    float* out = (float*)d_out;

    float *tln, *vln, *q, *k, *v, *attn, *o;
    cudaGetSymbolAddress((void**)&tln,  g_tln);
    cudaGetSymbolAddress((void**)&vln,  g_vln);
    cudaGetSymbolAddress((void**)&q,    g_q);
    cudaGetSymbolAddress((void**)&k,    g_k);
    cudaGetSymbolAddress((void**)&v,    g_v);
    cudaGetSymbolAddress((void**)&attn, g_attn);
    cudaGetSymbolAddress((void**)&o,    g_o);

    // LN1 on text and video
    ln_kernel<<<Tn, 128>>>(text, ln1g, ln1b, tln);
    ln_kernel<<<VFn, 128>>>(video, ln1g, ln1b, vln);

    // projections
    gemm_kernel<false><<<dim3(Tn / 128, 4), 256>>>(tln, Wq, bq, nullptr, q);
    gemm_kernel<false><<<dim3(VFn / 128, 4), 256>>>(vln, Wk, bk, nullptr, k);
    gemm_kernel<false><<<dim3(VFn / 128, 4), 256>>>(vln, Wv, bv, nullptr, v);

    // fused attention -> g_attn [V,T,E]
    cudaFuncSetAttribute(attn_kernel, cudaFuncAttributeMaxDynamicSharedMemorySize, 98304);
    attn_kernel<<<dim3(Vn, 4), 256, 98304>>>(q, k, v, attn);

    // o = attn @ Wo^T + bo  -> g_o
    gemm_kernel<false><<<dim3(Mbig / 128, 4), 256>>>(attn, Wo, bo, nullptr, o);

    // attn_out = LN2(o)  (in-place)
    ln_kernel<<<Mbig, 128>>>(o, ln2g, ln2b, o);

    // out_pre = attn_out @ Wl^T + bl + attn_out  -> d_out
    gemm_kernel<true><<<dim3(Mbig / 128, 4), 256>>>(o, Wl, bl, o, out);

    // out = LN3(out_pre)  (in-place)
    ln_kernel<<<Mbig, 128>>>(out, ln3g, ln3b, out);
}

// round 9
// speedup vs baseline: 1.1521x; 1.1521x over previous
#include <cuda_runtime.h>
#include <cuda_bf16.h>
#include <math.h>

#define Tn 512
#define Vn 512
#define Fn 12
#define En 512
#define Hn 8
#define Dn 64
#define VFn (Vn*Fn)
#define Mbig (Vn*Tn)

// ---------------- packed f32x2 macros (ptx_helpers.cuh idiom) ---------------
#define FFMA2(d, a, b) \
    asm("fma.rn.f32x2 %0, %1, %2, %3;" : "=l"(d) : "l"(a), "l"(b), "l"(d))
#define PACK2_DUP(out, x) \
    asm("mov.b64 %0, {%1, %1};" : "=l"(out) : "f"(x))
#define UNPACK2(lo, hi, v) \
    asm("mov.b64 {%0, %1}, %2;" : "=f"(lo), "=f"(hi) : "l"(v))

// ---------------- scratch (static device allocations; no cudaMalloc) ----------
static __device__ float g_tln[Tn*En];                 // 1 MB
static __device__ float g_vln[VFn*En];                // 12.6 MB
static __device__ float g_q[Tn*En];                   // 1 MB
static __device__ float g_k[VFn*En];                  // 12.6 MB
static __device__ float g_v[VFn*En];                  // 12.6 MB
static __device__ float g_attn[(size_t)Mbig*En];      // 512 MB
static __device__ float g_o[(size_t)Mbig*En];         // 512 MB

// ---------------- row LayerNorm over width 512 -------------------------------
// one block (128 threads) per row; each thread owns one float4
__global__ __launch_bounds__(128) void ln_kernel(
    const float* __restrict__ x, const float* __restrict__ g,
    const float* __restrict__ b, float* __restrict__ out)
{
    int row = blockIdx.x;
    int tid = threadIdx.x;
    const float4* x4 = (const float4*)(x + (size_t)row * En);
    float4 v = x4[tid];
    float s  = v.x + v.y + v.z + v.w;
    float ss = v.x*v.x + v.y*v.y + v.z*v.z + v.w*v.w;
    #pragma unroll
    for (int o = 16; o > 0; o >>= 1) {
        s  += __shfl_xor_sync(0xffffffffu, s,  o);
        ss += __shfl_xor_sync(0xffffffffu, ss, o);
    }
    __shared__ float sm[4], sm2[4];
    int w = tid >> 5, l = tid & 31;
    if (l == 0) { sm[w] = s; sm2[w] = ss; }
    __syncthreads();
    s  = sm[0] + sm[1] + sm[2] + sm[3];
    ss = sm2[0] + sm2[1] + sm2[2] + sm2[3];
    float mean = s * (1.0f / En);
    float var  = ss * (1.0f / En) - mean * mean;
    float rstd = rsqrtf(var + 1e-5f);
    float4 gg = ((const float4*)g)[tid];
    float4 bb = ((const float4*)b)[tid];
    float4 o;
    o.x = (v.x - mean) * rstd * gg.x + bb.x;
    o.y = (v.y - mean) * rstd * gg.y + bb.y;
    o.z = (v.z - mean) * rstd * gg.z + bb.z;
    o.w = (v.w - mean) * rstd * gg.w + bb.w;
    ((float4*)(out + (size_t)row * En))[tid] = o;
}

// ---------------- SIMT SGEMM with packed f32x2 FFMA2 -------------------------
// C[M,512] = A[M,512] @ W[512,512]^T + bias (+addsrc)
// BM=BN=128, BK=16, 256 threads, 8x8 per-thread tile, double-buffered smem
template<bool ADD>
__global__ __launch_bounds__(256, 2) void gemm_kernel(
    const float* __restrict__ A, const float* __restrict__ W,
    const float* __restrict__ bias, const float* __restrict__ addsrc,
    float* __restrict__ C)
{
    constexpr int BM = 128, BK = 16, LDS_P = BM + 4;
    __shared__ float As[2][BK][LDS_P];
    __shared__ float Bs[2][BK][LDS_P];

    int tid = threadIdx.x;
    int bm = blockIdx.x, bn = blockIdx.y;
    int tx = tid & 15, ty = tid >> 4;

    const float* Ab = A + (size_t)bm * BM * 512;
    const float* Wb = W + (size_t)bn * BM * 512;

    unsigned long long acc2[8][4];
    #pragma unroll
    for (int i = 0; i < 8; i++)
        #pragma unroll
        for (int j = 0; j < 4; j++) acc2[i][j] = 0ULL;   // {0.0f, 0.0f}

    float pa[8], pb[8];

    // prologue: tile 0 -> smem[0]
    {
        int k0 = 0;
        #pragma unroll
        for (int it = 0; it < 2; it++) {
            int r = tid + 256 * it;
            int row = r >> 2, kc = (r & 3) << 2;
            float4 va = *(const float4*)(Ab + (size_t)row * 512 + k0 + kc);
            float4 vb = *(const float4*)(Wb + (size_t)row * 512 + k0 + kc);
            As[0][kc + 0][row] = va.x; As[0][kc + 1][row] = va.y;
            As[0][kc + 2][row] = va.z; As[0][kc + 3][row] = va.w;
            Bs[0][kc + 0][row] = vb.x; Bs[0][kc + 1][row] = vb.y;
            Bs[0][kc + 2][row] = vb.z; Bs[0][kc + 3][row] = vb.w;
        }
    }
    __syncthreads();

    const int NT = 512 / BK; // 32
    for (int kt = 0; kt < NT; kt++) {
        int cur = kt & 1;
        if (kt + 1 < NT) {
            int k0 = (kt + 1) * BK;
            #pragma unroll
            for (int it = 0; it < 2; it++) {
                int r = tid + 256 * it;
                int row = r >> 2, kc = (r & 3) << 2;
                float4 va = *(const float4*)(Ab + (size_t)row * 512 + k0 + kc);
                float4 vb = *(const float4*)(Wb + (size_t)row * 512 + k0 + kc);
                pa[it*4+0] = va.x; pa[it*4+1] = va.y; pa[it*4+2] = va.z; pa[it*4+3] = va.w;
                pb[it*4+0] = vb.x; pb[it*4+1] = vb.y; pb[it*4+2] = vb.z; pb[it*4+3] = vb.w;
            }
        }
        #pragma unroll
        for (int k = 0; k < BK; k++) {
            float a[8];
            *(float4*)(a)     = *(const float4*)&As[cur][k][ty * 8];
            *(float4*)(a + 4) = *(const float4*)&As[cur][k][ty * 8 + 4];
            const unsigned long long* bp =
                (const unsigned long long*)&Bs[cur][k][tx * 8];
            unsigned long long b0 = bp[0], b1 = bp[1], b2 = bp[2], b3 = bp[3];
            #pragma unroll
            for (int i = 0; i < 8; i++) {
                unsigned long long a2;
                PACK2_DUP(a2, a[i]);
                FFMA2(acc2[i][0], a2, b0);
                FFMA2(acc2[i][1], a2, b1);
                FFMA2(acc2[i][2], a2, b2);
                FFMA2(acc2[i][3], a2, b3);
            }
        }
        if (kt + 1 < NT) {
            int nb = (kt + 1) & 1;
            #pragma unroll
            for (int it = 0; it < 2; it++) {
                int r = tid + 256 * it;
                int row = r >> 2, kc = (r & 3) << 2;
                As[nb][kc + 0][row] = pa[it*4+0]; As[nb][kc + 1][row] = pa[it*4+1];
                As[nb][kc + 2][row] = pa[it*4+2]; As[nb][kc + 3][row] = pa[it*4+3];
                Bs[nb][kc + 0][row] = pb[it*4+0]; Bs[nb][kc + 1][row] = pb[it*4+1];
                Bs[nb][kc + 2][row] = pb[it*4+2]; Bs[nb][kc + 3][row] = pb[it*4+3];
            }
            __syncthreads();
        }
    }

    int row0 = bm * BM + ty * 8;
    int col0 = bn * BM + tx * 8;
    float4 bi0 = *(const float4*)(bias + col0);
    float4 bi1 = *(const float4*)(bias + col0 + 4);
    #pragma unroll
    for (int i = 0; i < 8; i++) {
        size_t base = (size_t)(row0 + i) * 512 + col0;
        float c0, c1, c2, c3, c4, c5, c6, c7;
        UNPACK2(c0, c1, acc2[i][0]);
        UNPACK2(c2, c3, acc2[i][1]);
        UNPACK2(c4, c5, acc2[i][2]);
        UNPACK2(c6, c7, acc2[i][3]);
        float4 v0, v1;
        v0.x = c0 + bi0.x; v0.y = c1 + bi0.y;
        v0.z = c2 + bi0.z; v0.w = c3 + bi0.w;
        v1.x = c4 + bi1.x; v1.y = c5 + bi1.y;
        v1.z = c6 + bi1.z; v1.w = c7 + bi1.w;
        if (ADD) {
            float4 a0 = *(const float4*)(addsrc + base);
            float4 a1 = *(const float4*)(addsrc + base + 4);
            v0.x += a0.x; v0.y += a0.y; v0.z += a0.z; v0.w += a0.w;
            v1.x += a1.x; v1.y += a1.y; v1.z += a1.z; v1.w += a1.w;
        }
        *(float4*)(C + base)     = v0;
        *(float4*)(C + base + 4) = v1;
    }
}

// ---------------- fused attention: logits + softmax(frames) + weighted sum ----
// grid: (V, T/128).  block: 256 threads.
// smem: k_s[12][512], v_s[12][512], w_s[8][12][128]  = 96 KB dynamic
__global__ __launch_bounds__(256) void attn_kernel(
    const float* __restrict__ q, const float* __restrict__ kk,
    const float* __restrict__ vv, float* __restrict__ attn)
{
    extern __shared__ float smem[];
    float* k_s = smem;                    // 12*512
    float* v_s = smem + Fn * En;          // 12*512
    float* w_s = smem + 2 * Fn * En;      // 8*12*128

    int vb  = blockIdx.x;
    int tt  = blockIdx.y;                 // t-tile of 128
    int tid = threadIdx.x;

    // stage k,v for this video
    {
        const float4* kg = (const float4*)(kk + (size_t)vb * Fn * En);
        const float4* vg = (const float4*)(vv + (size_t)vb * Fn * En);
        float4* k4 = (float4*)k_s;
        float4* v4 = (float4*)v_s;
        for (int i = tid; i < Fn * En / 4; i += 256) { k4[i] = kg[i]; v4[i] = vg[i]; }
    }
    __syncthreads();

    // ---- logits + softmax: warp h owns head h; lane owns 4 t-rows -----------
    int h = tid >> 5, lane = tid & 31;
    int tbase = tt * 128 + lane * 4;

    float acc[Fn][4];
    #pragma unroll
    for (int f = 0; f < Fn; f++)
        #pragma unroll
        for (int i = 0; i < 4; i++) acc[f][i] = 0.0f;

    const float* q0 = q + (size_t)(tbase + 0) * En + h * Dn;
    const float* q1 = q + (size_t)(tbase + 1) * En + h * Dn;
    const float* q2 = q + (size_t)(tbase + 2) * En + h * Dn;
    const float* q3 = q + (size_t)(tbase + 3) * En + h * Dn;
    const float* kb = k_s + h * Dn;

    for (int dc = 0; dc < Dn; dc += 8) {
        float qf[4][8];
        *(float4*)&qf[0][0] = *(const float4*)(q0 + dc);
        *(float4*)&qf[0][4] = *(const float4*)(q0 + dc + 4);
        *(float4*)&qf[1][0] = *(const float4*)(q1 + dc);
        *(float4*)&qf[1][4] = *(const float4*)(q1 + dc + 4);
        *(float4*)&qf[2][0] = *(const float4*)(q2 + dc);
        *(float4*)&qf[2][4] = *(const float4*)(q2 + dc + 4);
        *(float4*)&qf[3][0] = *(const float4*)(q3 + dc);
        *(float4*)&qf[3][4] = *(const float4*)(q3 + dc + 4);
        #pragma unroll
        for (int d = 0; d < 8; d++) {
            #pragma unroll
            for (int f = 0; f < Fn; f++) {
                float kv = kb[f * En + dc + d];   // broadcast within warp
                #pragma unroll
                for (int i = 0; i < 4; i++)
                    acc[f][i] = fmaf(kv, qf[i][d], acc[f][i]);
            }
        }
    }

    const float scale = 0.125f; // 1/sqrt(64)
    #pragma unroll
    for (int i = 0; i < 4; i++) {
        float m = -1e30f;
        #pragma unroll
        for (int f = 0; f < Fn; f++) m = fmaxf(m, acc[f][i] * scale);
        float e[Fn];
        float s = 0.0f;
        #pragma unroll
        for (int f = 0; f < Fn; f++) { e[f] = __expf(acc[f][i] * scale - m); s += e[f]; }
        float inv = 1.0f / s;
        #pragma unroll
        for (int f = 0; f < Fn; f++)
            w_s[(h * Fn + f) * 128 + lane * 4 + i] = e[f] * inv;
    }
    __syncthreads();

    // ---- attn = sum_f w * v ; thread owns an e-quad, loops 64 t-rows --------
    int ec   = tid & 127;
    int half = tid >> 7;
    int e0   = ec * 4;
    int hh   = e0 >> 6;
    #pragma unroll 4
    for (int tl = 0; tl < 64; tl++) {
        int t_local = half * 64 + tl;
        float4 o = make_float4(0.f, 0.f, 0.f, 0.f);
        #pragma unroll
        for (int f = 0; f < Fn; f++) {
            float w   = w_s[(hh * Fn + f) * 128 + t_local];
            float4 vq = *(const float4*)&v_s[f * En + e0];
            o.x = fmaf(w, vq.x, o.x);
            o.y = fmaf(w, vq.y, o.y);
            o.z = fmaf(w, vq.z, o.z);
            o.w = fmaf(w, vq.w, o.w);
        }
        size_t t = (size_t)tt * 128 + t_local;
        *(float4*)(attn + ((size_t)vb * Tn + t) * En + e0) = o;
    }
}

// ---------------- launch ------------------------------------------------------
extern "C" void kernel_launch(void* const* d_in, const int* in_sizes, int n_in,
                              void* d_out, int out_size)
{
    const float* text  = (const float*)d_in[0];
    const float* video = (const float*)d_in[1];
    const float* Wq = (const float*)d_in[2];  const float* bq = (const float*)d_in[3];
    const float* Wk = (const float*)d_in[4];  const float* bk = (const float*)d_in[5];
    const float* Wv = (const float*)d_in[6];  const float* bv = (const float*)d_in[7];
    const float* Wo = (const float*)d_in[8];  const float* bo = (const float*)d_in[9];
    const float* Wl = (const float*)d_in[10]; const float* bl = (const float*)d_in[11];
    const float* ln1g = (const float*)d_in[12]; const float* ln1b = (const float*)d_in[13];
    const float* ln2g = (const float*)d_in[14]; const float* ln2b = (const float*)d_in[15];
    const float* ln3g = (const float*)d_in[16]; const float* ln3b = (const float*)d_in[17];
    float* out = (float*)d_out;

    float *tln, *vln, *q, *k, *v, *attn, *o;
    cudaGetSymbolAddress((void**)&tln,  g_tln);
    cudaGetSymbolAddress((void**)&vln,  g_vln);
    cudaGetSymbolAddress((void**)&q,    g_q);
    cudaGetSymbolAddress((void**)&k,    g_k);
    cudaGetSymbolAddress((void**)&v,    g_v);
    cudaGetSymbolAddress((void**)&attn, g_attn);
    cudaGetSymbolAddress((void**)&o,    g_o);

    // LN1 on text and video
    ln_kernel<<<Tn, 128>>>(text, ln1g, ln1b, tln);
    ln_kernel<<<VFn, 128>>>(video, ln1g, ln1b, vln);

    // projections
    gemm_kernel<false><<<dim3(Tn / 128, 4), 256>>>(tln, Wq, bq, nullptr, q);
    gemm_kernel<false><<<dim3(VFn / 128, 4), 256>>>(vln, Wk, bk, nullptr, k);
    gemm_kernel<false><<<dim3(VFn / 128, 4), 256>>>(vln, Wv, bv, nullptr, v);

    // fused attention -> g_attn [V,T,E]
    cudaFuncSetAttribute(attn_kernel, cudaFuncAttributeMaxDynamicSharedMemorySize, 98304);
    attn_kernel<<<dim3(Vn, 4), 256, 98304>>>(q, k, v, attn);

    // o = attn @ Wo^T + bo  -> g_o
    gemm_kernel<false><<<dim3(Mbig / 128, 4), 256>>>(attn, Wo, bo, nullptr, o);

    // attn_out = LN2(o)  (in-place)
    ln_kernel<<<Mbig, 128>>>(o, ln2g, ln2b, o);

    // out_pre = attn_out @ Wl^T + bl + attn_out  -> d_out
    gemm_kernel<true><<<dim3(Mbig / 128, 4), 256>>>(o, Wl, bl, o, out);

    // out = LN3(out_pre)  (in-place)
    ln_kernel<<<Mbig, 128>>>(out, ln3g, ln3b, out);
}

// round 13
// speedup vs baseline: 2.0983x; 1.8214x over previous
#include <cuda_runtime.h>
#include <cuda_bf16.h>
#include <math.h>

#define Tn 512
#define Vn 512
#define Fn 12
#define En 512
#define Hn 8
#define Dn 64
#define VFn (Vn*Fn)
#define Mbig (Vn*Tn)

// ---------------- mma.sync / ldmatrix macros (<=10 operands) -----------------
#define LDSM_X4(r0, r1, r2, r3, addr) \
    asm volatile("ldmatrix.sync.aligned.m8n8.x4.shared.b16 {%0,%1,%2,%3}, [%4];" \
                 : "=r"(r0), "=r"(r1), "=r"(r2), "=r"(r3) : "r"(addr))
#define LDSM_X2(r0, r1, addr) \
    asm volatile("ldmatrix.sync.aligned.m8n8.x2.shared.b16 {%0,%1}, [%2];" \
                 : "=r"(r0), "=r"(r1) : "r"(addr))
#define MMA16816(d0, d1, d2, d3, a0, a1, a2, a3, b0, b1) \
    asm volatile("mma.sync.aligned.m16n8k16.row.col.f32.bf16.bf16.f32 " \
                 "{%0,%1,%2,%3}, {%4,%5,%6,%7}, {%8,%9}, {%0,%1,%2,%3};" \
                 : "+f"(d0), "+f"(d1), "+f"(d2), "+f"(d3) \
                 : "r"(a0), "r"(a1), "r"(a2), "r"(a3), "r"(b0), "r"(b1))

// split fp32 v (float4) into bf16 hi/lo; store 4 elems at [r][c] (24-elem rows)
#define CVT_STORE(dsthi, dstlo, r, c, v) do { \
    __nv_bfloat16 h0 = __float2bfloat16((v).x); \
    __nv_bfloat16 h1 = __float2bfloat16((v).y); \
    __nv_bfloat16 h2 = __float2bfloat16((v).z); \
    __nv_bfloat16 h3 = __float2bfloat16((v).w); \
    __nv_bfloat16 l0 = __float2bfloat16((v).x - __bfloat162float(h0)); \
    __nv_bfloat16 l1 = __float2bfloat16((v).y - __bfloat162float(h1)); \
    __nv_bfloat16 l2 = __float2bfloat16((v).z - __bfloat162float(h2)); \
    __nv_bfloat16 l3 = __float2bfloat16((v).w - __bfloat162float(h3)); \
    __nv_bfloat162 hp0; hp0.x = h0; hp0.y = h1; \
    __nv_bfloat162 hp1; hp1.x = h2; hp1.y = h3; \
    __nv_bfloat162 lp0; lp0.x = l0; lp0.y = l1; \
    __nv_bfloat162 lp1; lp1.x = l2; lp1.y = l3; \
    *(__nv_bfloat162*)(&(dsthi)[(r) * 24 + (c)])     = hp0; \
    *(__nv_bfloat162*)(&(dsthi)[(r) * 24 + (c) + 2]) = hp1; \
    *(__nv_bfloat162*)(&(dstlo)[(r) * 24 + (c)])     = lp0; \
    *(__nv_bfloat162*)(&(dstlo)[(r) * 24 + (c) + 2]) = lp1; \
} while (0)

// dynamic-smem layout: 4 regions x 2 stages x (128*24) bf16 = 49152 bytes
#define STAGE_ELEMS (128 * 24)
#define MGEMM_SMEM  (4 * 2 * STAGE_ELEMS * 2)

// ---------------- scratch ----------------------------------------------------
static __device__ float g_tln[Tn*En];
static __device__ float g_vln[VFn*En];
static __device__ float g_q[Tn*En];
static __device__ float g_k[VFn*En];
static __device__ float g_v[VFn*En];
static __device__ float g_attn[(size_t)Mbig*En];      // 512 MB
static __device__ float g_o[(size_t)Mbig*En];         // 512 MB

// ---------------- row LayerNorm over width 512 -------------------------------
__global__ __launch_bounds__(128) void ln_kernel(
    const float* __restrict__ x, const float* __restrict__ g,
    const float* __restrict__ b, float* __restrict__ out)
{
    int row = blockIdx.x;
    int tid = threadIdx.x;
    const float4* x4 = (const float4*)(x + (size_t)row * En);
    float4 v = x4[tid];
    float s  = v.x + v.y + v.z + v.w;
    float ss = v.x*v.x + v.y*v.y + v.z*v.z + v.w*v.w;
    #pragma unroll
    for (int o = 16; o > 0; o >>= 1) {
        s  += __shfl_xor_sync(0xffffffffu, s,  o);
        ss += __shfl_xor_sync(0xffffffffu, ss, o);
    }
    __shared__ float sm[4], sm2[4];
    int w = tid >> 5, l = tid & 31;
    if (l == 0) { sm[w] = s; sm2[w] = ss; }
    __syncthreads();
    s  = sm[0] + sm[1] + sm[2] + sm[3];
    ss = sm2[0] + sm2[1] + sm2[2] + sm2[3];
    float mean = s * (1.0f / En);
    float var  = ss * (1.0f / En) - mean * mean;
    float rstd = rsqrtf(var + 1e-5f);
    float4 gg = ((const float4*)g)[tid];
    float4 bb = ((const float4*)b)[tid];
    float4 o;
    o.x = (v.x - mean) * rstd * gg.x + bb.x;
    o.y = (v.y - mean) * rstd * gg.y + bb.y;
    o.z = (v.z - mean) * rstd * gg.z + bb.z;
    o.w = (v.w - mean) * rstd * gg.w + bb.w;
    ((float4*)(out + (size_t)row * En))[tid] = o;
}

// ---------------- tensor-core GEMM (mma.sync bf16, 3-term split) -------------
// C[M,512] = A[M,512] @ W[512,512]^T + bias (+addsrc), fp32 in/out.
// CTA tile 128x128, 8 warps in 4x2 (warp tile 32x64), BK=16, double-buffered.
// SMEM rows padded to 24 bf16 (48B, 16B-multiple) -> aligned, conflict-free
// ldmatrix. All tile buffers in DYNAMIC smem (16B-aligned carve, no 48KB
// static-limit edge).
template<bool ADD>
__global__ __launch_bounds__(256) void mgemm_kernel(
    const float* __restrict__ A, const float* __restrict__ W,
    const float* __restrict__ bias, const float* __restrict__ addsrc,
    float* __restrict__ C)
{
    extern __shared__ __align__(16) char dynsm[];
    __nv_bfloat16* sAhi = (__nv_bfloat16*)(dynsm);
    __nv_bfloat16* sAlo = sAhi + 2 * STAGE_ELEMS;
    __nv_bfloat16* sWhi = sAlo + 2 * STAGE_ELEMS;
    __nv_bfloat16* sWlo = sWhi + 2 * STAGE_ELEMS;

    int tid = threadIdx.x;
    int wid = tid >> 5, lane = tid & 31;
    int bm = blockIdx.x, bn = blockIdx.y;
    int warp_m = (wid >> 1) * 32;
    int warp_n = (wid & 1) * 64;

    const float* Ab = A + (size_t)bm * 128 * 512;
    const float* Wb = W + (size_t)bn * 128 * 512;

    float acc[2][8][4];
    #pragma unroll
    for (int im = 0; im < 2; im++)
        #pragma unroll
        for (int jn = 0; jn < 8; jn++)
            #pragma unroll
            for (int e = 0; e < 4; e++) acc[im][jn][e] = 0.0f;

    int rs = tid >> 2;          // 0..63 (it adds 64)
    int cs = (tid & 3) * 4;     // 0,4,8,12

    // stage chunk 0 -> buffer 0
    #pragma unroll
    for (int it = 0; it < 2; it++) {
        int r = rs + 64 * it;
        float4 va = *(const float4*)(Ab + (size_t)r * 512 + cs);
        float4 vw = *(const float4*)(Wb + (size_t)r * 512 + cs);
        CVT_STORE(sAhi, sAlo, r, cs, va);
        CVT_STORE(sWhi, sWlo, r, cs, vw);
    }
    __syncthreads();

    float4 pa[2], pw[2];
    for (int kt = 0; kt < 32; kt++) {
        int cur = kt & 1;
        if (kt + 1 < 32) {
            int k0 = (kt + 1) * 16;
            #pragma unroll
            for (int it = 0; it < 2; it++) {
                int r = rs + 64 * it;
                pa[it] = *(const float4*)(Ab + (size_t)r * 512 + k0 + cs);
                pw[it] = *(const float4*)(Wb + (size_t)r * 512 + k0 + cs);
            }
        }

        unsigned aHi = (unsigned)__cvta_generic_to_shared(sAhi + cur * STAGE_ELEMS);
        unsigned aLo = (unsigned)__cvta_generic_to_shared(sAlo + cur * STAGE_ELEMS);
        unsigned wHi = (unsigned)__cvta_generic_to_shared(sWhi + cur * STAGE_ELEMS);
        unsigned wLo = (unsigned)__cvta_generic_to_shared(sWlo + cur * STAGE_ELEMS);

        unsigned ah[2][4], al[2][4], bh[8][2], bl[8][2];
        #pragma unroll
        for (int im = 0; im < 2; im++) {
            unsigned off = ((unsigned)(warp_m + im * 16 + (lane & 15)) * 24u
                            + (((unsigned)lane >> 4) << 3)) * 2u;
            LDSM_X4(ah[im][0], ah[im][1], ah[im][2], ah[im][3], aHi + off);
            LDSM_X4(al[im][0], al[im][1], al[im][2], al[im][3], aLo + off);
        }
        #pragma unroll
        for (int jn = 0; jn < 8; jn++) {
            unsigned off = ((unsigned)(warp_n + jn * 8 + (lane & 7)) * 24u
                            + ((((unsigned)lane >> 3) & 1u) << 3)) * 2u;
            LDSM_X2(bh[jn][0], bh[jn][1], wHi + off);
            LDSM_X2(bl[jn][0], bl[jn][1], wLo + off);
        }

        #pragma unroll
        for (int im = 0; im < 2; im++) {
            #pragma unroll
            for (int jn = 0; jn < 8; jn++) {
                MMA16816(acc[im][jn][0], acc[im][jn][1], acc[im][jn][2], acc[im][jn][3],
                         ah[im][0], ah[im][1], ah[im][2], ah[im][3],
                         bh[jn][0], bh[jn][1]);
                MMA16816(acc[im][jn][0], acc[im][jn][1], acc[im][jn][2], acc[im][jn][3],
                         ah[im][0], ah[im][1], ah[im][2], ah[im][3],
                         bl[jn][0], bl[jn][1]);
                MMA16816(acc[im][jn][0], acc[im][jn][1], acc[im][jn][2], acc[im][jn][3],
                         al[im][0], al[im][1], al[im][2], al[im][3],
                         bh[jn][0], bh[jn][1]);
            }
        }

        if (kt + 1 < 32) {
            __syncthreads();
            int nb = cur ^ 1;
            __nv_bfloat16* dAhi = sAhi + nb * STAGE_ELEMS;
            __nv_bfloat16* dAlo = sAlo + nb * STAGE_ELEMS;
            __nv_bfloat16* dWhi = sWhi + nb * STAGE_ELEMS;
            __nv_bfloat16* dWlo = sWlo + nb * STAGE_ELEMS;
            #pragma unroll
            for (int it = 0; it < 2; it++) {
                int r = rs + 64 * it;
                CVT_STORE(dAhi, dAlo, r, cs, pa[it]);
                CVT_STORE(dWhi, dWlo, r, cs, pw[it]);
            }
            __syncthreads();
        }
    }

    // epilogue: c0,c1 -> (row, col..col+1); c2,c3 -> (row+8, col..col+1)
    #pragma unroll
    for (int im = 0; im < 2; im++) {
        #pragma unroll
        for (int jn = 0; jn < 8; jn++) {
            int gr = bm * 128 + warp_m + im * 16 + (lane >> 2);
            int gc = bn * 128 + warp_n + jn * 8 + (lane & 3) * 2;
            float2 b2 = *(const float2*)(bias + gc);
            size_t base0 = (size_t)gr * 512 + gc;
            size_t base1 = (size_t)(gr + 8) * 512 + gc;
            float2 v0, v1;
            v0.x = acc[im][jn][0] + b2.x; v0.y = acc[im][jn][1] + b2.y;
            v1.x = acc[im][jn][2] + b2.x; v1.y = acc[im][jn][3] + b2.y;
            if (ADD) {
                float2 a0 = *(const float2*)(addsrc + base0);
                float2 a1 = *(const float2*)(addsrc + base1);
                v0.x += a0.x; v0.y += a0.y;
                v1.x += a1.x; v1.y += a1.y;
            }
            *(float2*)(C + base0) = v0;
            *(float2*)(C + base1) = v1;
        }
    }
}

// ---------------- fused attention (unchanged, fp32) --------------------------
__global__ __launch_bounds__(256) void attn_kernel(
    const float* __restrict__ q, const float* __restrict__ kk,
    const float* __restrict__ vv, float* __restrict__ attn)
{
    extern __shared__ float smem[];
    float* k_s = smem;
    float* v_s = smem + Fn * En;
    float* w_s = smem + 2 * Fn * En;

    int vb  = blockIdx.x;
    int tt  = blockIdx.y;
    int tid = threadIdx.x;

    {
        const float4* kg = (const float4*)(kk + (size_t)vb * Fn * En);
        const float4* vg = (const float4*)(vv + (size_t)vb * Fn * En);
        float4* k4 = (float4*)k_s;
        float4* v4 = (float4*)v_s;
        for (int i = tid; i < Fn * En / 4; i += 256) { k4[i] = kg[i]; v4[i] = vg[i]; }
    }
    __syncthreads();

    int h = tid >> 5, lane = tid & 31;
    int tbase = tt * 128 + lane * 4;

    float acc[Fn][4];
    #pragma unroll
    for (int f = 0; f < Fn; f++)
        #pragma unroll
        for (int i = 0; i < 4; i++) acc[f][i] = 0.0f;

    const float* q0 = q + (size_t)(tbase + 0) * En + h * Dn;
    const float* q1 = q + (size_t)(tbase + 1) * En + h * Dn;
    const float* q2 = q + (size_t)(tbase + 2) * En + h * Dn;
    const float* q3 = q + (size_t)(tbase + 3) * En + h * Dn;
    const float* kb = k_s + h * Dn;

    for (int dc = 0; dc < Dn; dc += 8) {
        float qf[4][8];
        *(float4*)&qf[0][0] = *(const float4*)(q0 + dc);
        *(float4*)&qf[0][4] = *(const float4*)(q0 + dc + 4);
        *(float4*)&qf[1][0] = *(const float4*)(q1 + dc);
        *(float4*)&qf[1][4] = *(const float4*)(q1 + dc + 4);
        *(float4*)&qf[2][0] = *(const float4*)(q2 + dc);
        *(float4*)&qf[2][4] = *(const float4*)(q2 + dc + 4);
        *(float4*)&qf[3][0] = *(const float4*)(q3 + dc);
        *(float4*)&qf[3][4] = *(const float4*)(q3 + dc + 4);
        #pragma unroll
        for (int d = 0; d < 8; d++) {
            #pragma unroll
            for (int f = 0; f < Fn; f++) {
                float kv = kb[f * En + dc + d];
                #pragma unroll
                for (int i = 0; i < 4; i++)
                    acc[f][i] = fmaf(kv, qf[i][d], acc[f][i]);
            }
        }
    }

    const float scale = 0.125f;
    #pragma unroll
    for (int i = 0; i < 4; i++) {
        float m = -1e30f;
        #pragma unroll
        for (int f = 0; f < Fn; f++) m = fmaxf(m, acc[f][i] * scale);
        float e[Fn];
        float s = 0.0f;
        #pragma unroll
        for (int f = 0; f < Fn; f++) { e[f] = __expf(acc[f][i] * scale - m); s += e[f]; }
        float inv = 1.0f / s;
        #pragma unroll
        for (int f = 0; f < Fn; f++)
            w_s[(h * Fn + f) * 128 + lane * 4 + i] = e[f] * inv;
    }
    __syncthreads();

    int ec   = tid & 127;
    int half = tid >> 7;
    int e0   = ec * 4;
    int hh   = e0 >> 6;
    #pragma unroll 4
    for (int tl = 0; tl < 64; tl++) {
        int t_local = half * 64 + tl;
        float4 o = make_float4(0.f, 0.f, 0.f, 0.f);
        #pragma unroll
        for (int f = 0; f < Fn; f++) {
            float w   = w_s[(hh * Fn + f) * 128 + t_local];
            float4 vq = *(const float4*)&v_s[f * En + e0];
            o.x = fmaf(w, vq.x, o.x);
            o.y = fmaf(w, vq.y, o.y);
            o.z = fmaf(w, vq.z, o.z);
            o.w = fmaf(w, vq.w, o.w);
        }
        size_t t = (size_t)tt * 128 + t_local;
        *(float4*)(attn + ((size_t)vb * Tn + t) * En + e0) = o;
    }
}

// ---------------- launch ------------------------------------------------------
extern "C" void kernel_launch(void* const* d_in, const int* in_sizes, int n_in,
                              void* d_out, int out_size)
{
    const float* text  = (const float*)d_in[0];
    const float* video = (const float*)d_in[1];
    const float* Wq = (const float*)d_in[2];  const float* bq = (const float*)d_in[3];
    const float* Wk = (const float*)d_in[4];  const float* bk = (const float*)d_in[5];
    const float* Wv = (const float*)d_in[6];  const float* bv = (const float*)d_in[7];
    const float* Wo = (const float*)d_in[8];  const float* bo = (const float*)d_in[9];
    const float* Wl = (const float*)d_in[10]; const float* bl = (const float*)d_in[11];
    const float* ln1g = (const float*)d_in[12]; const float* ln1b = (const float*)d_in[13];
    const float* ln2g = (const float*)d_in[14]; const float* ln2b = (const float*)d_in[15];
    const float* ln3g = (const float*)d_in[16]; const float* ln3b = (const float*)d_in[17];
    float* out = (float*)d_out;

    float *tln, *vln, *q, *k, *v, *attn, *o;
    cudaGetSymbolAddress((void**)&tln,  g_tln);
    cudaGetSymbolAddress((void**)&vln,  g_vln);
    cudaGetSymbolAddress((void**)&q,    g_q);
    cudaGetSymbolAddress((void**)&k,    g_k);
    cudaGetSymbolAddress((void**)&v,    g_v);
    cudaGetSymbolAddress((void**)&attn, g_attn);
    cudaGetSymbolAddress((void**)&o,    g_o);

    cudaFuncSetAttribute(mgemm_kernel<false>, cudaFuncAttributeMaxDynamicSharedMemorySize, MGEMM_SMEM);
    cudaFuncSetAttribute(mgemm_kernel<true>,  cudaFuncAttributeMaxDynamicSharedMemorySize, MGEMM_SMEM);
    cudaFuncSetAttribute(attn_kernel, cudaFuncAttributeMaxDynamicSharedMemorySize, 98304);

    // LN1 on text and video
    ln_kernel<<<Tn, 128>>>(text, ln1g, ln1b, tln);
    ln_kernel<<<VFn, 128>>>(video, ln1g, ln1b, vln);

    // projections (tensor cores, bf16 split)
    mgemm_kernel<false><<<dim3(Tn / 128, 4), 256, MGEMM_SMEM>>>(tln, Wq, bq, nullptr, q);
    mgemm_kernel<false><<<dim3(VFn / 128, 4), 256, MGEMM_SMEM>>>(vln, Wk, bk, nullptr, k);
    mgemm_kernel<false><<<dim3(VFn / 128, 4), 256, MGEMM_SMEM>>>(vln, Wv, bv, nullptr, v);

    // fused attention -> g_attn [V,T,E]
    attn_kernel<<<dim3(Vn, 4), 256, 98304>>>(q, k, v, attn);

    // o = attn @ Wo^T + bo
    mgemm_kernel<false><<<dim3(Mbig / 128, 4), 256, MGEMM_SMEM>>>(attn, Wo, bo, nullptr, o);

    // attn_out = LN2(o) in-place
    ln_kernel<<<Mbig, 128>>>(o, ln2g, ln2b, o);

    // out_pre = attn_out @ Wl^T + bl + attn_out
    mgemm_kernel<true><<<dim3(Mbig / 128, 4), 256, MGEMM_SMEM>>>(o, Wl, bl, o, out);

    // out = LN3(out_pre) in-place
    ln_kernel<<<Mbig, 128>>>(out, ln3g, ln3b, out);
}